// round 1
// baseline (speedup 1.0000x reference)
#include <cuda_runtime.h>
#include <cuda_bf16.h>

// GAE backward scan. Inputs (metadata order): rewards f32 [B,S], values f32 [B,S],
// dones i32 [B,S], mask i32 [B,S] (prefix mask). Output: [advantages; returns],
// 2*B*S floats.
//
// Recurrence (reverse over t):
//   nd    = 1 - done
//   nv[t] = values[t+1] * mask[t+1]           (0 at last valid step / t=S-1)
//   delta = r + GAMMA*nv*nd - v
//   g[t]  = mask[t] ? (delta + GAMMA*LAMBDA*nd * g[t+1]) : 0
//   adv = g ; ret = mask ? g + v : 0
//
// Parallelized as an affine suffix scan: T_t(g) = d_t + c_t*g, with
// (c,d) = mask ? (GAMMA*LAMBDA*nd, delta) : (0,0).   Composition
// (left earlier-in-time): a = la*ra, b = lb + la*rb.

#define GAMMA  0.999f
#define LAMBDA 0.95f
#define S_LEN  2048
#define TPB    512
#define EPT    4   // elements per thread: TPB*EPT == S_LEN

__global__ __launch_bounds__(TPB, 4)
void gae_kernel(const float* __restrict__ rewards,
                const float* __restrict__ values,
                const int*   __restrict__ dones,
                const int*   __restrict__ mask,
                float* __restrict__ adv_out,
                float* __restrict__ ret_out)
{
    const int row  = blockIdx.x;
    const int tid  = threadIdx.x;
    const unsigned lane = tid & 31u;
    const unsigned warp = tid >> 5;

    const long long base = (long long)row * S_LEN + tid * EPT;

    // Coalesced vector loads of this thread's 4 contiguous timesteps.
    const float4 r4 = *reinterpret_cast<const float4*>(rewards + base);
    const float4 v4 = *reinterpret_cast<const float4*>(values  + base);
    const int4   d4 = *reinterpret_cast<const int4*>(dones + base);
    const int4   m4 = *reinterpret_cast<const int4*>(mask  + base);

    // Neighbor (t+1) values/mask for the last element of this thread's chunk.
    float v_next = 0.f;
    float m_next = 0.f;
    if (tid * EPT + EPT < S_LEN) {
        v_next = values[base + EPT];              // L1/L2 hit (neighbor's data)
        m_next = (float)mask[base + EPT];
    }

    float r[EPT]  = {r4.x, r4.y, r4.z, r4.w};
    float v[EPT]  = {v4.x, v4.y, v4.z, v4.w};
    float nd[EPT] = {1.f - (float)d4.x, 1.f - (float)d4.y,
                     1.f - (float)d4.z, 1.f - (float)d4.w};
    float mk[EPT] = {(float)m4.x, (float)m4.y, (float)m4.z, (float)m4.w};
    float nv[EPT]     = {v[1], v[2], v[3], v_next};
    float mnext[EPT]  = {mk[1], mk[2], mk[3], m_next};

    // Per-element affine transforms (c, d); invalid steps -> (0, 0).
    float c[EPT], d[EPT];
#pragma unroll
    for (int j = 0; j < EPT; ++j) {
        float nvj   = nv[j] * mnext[j];                       // zero past last valid
        float delta = fmaf(GAMMA * nd[j], nvj, r[j]) - v[j];
        c[j] = mk[j] * (GAMMA * LAMBDA) * nd[j];
        d[j] = mk[j] * delta;
    }

    // Thread-local composition over its 4 steps (reverse time order).
    float A = 1.f, B = 0.f;
#pragma unroll
    for (int j = EPT - 1; j >= 0; --j) {
        B = fmaf(c[j], B, d[j]);
        A = c[j] * A;
    }

    // Warp-level inclusive suffix scan (Kogge-Stone via shfl_down).
    float a = A, b = B;
#pragma unroll
    for (int off = 1; off < 32; off <<= 1) {
        float ra = __shfl_down_sync(0xffffffffu, a, off);
        float rb = __shfl_down_sync(0xffffffffu, b, off);
        if (lane + off < 32) {
            b = fmaf(a, rb, b);
            a = a * ra;
        }
    }
    // Exclusive suffix within warp: E_i = inclusive(i+1); identity at lane 31.
    float ea = __shfl_down_sync(0xffffffffu, a, 1);
    float eb = __shfl_down_sync(0xffffffffu, b, 1);
    if (lane == 31) { ea = 1.f; eb = 0.f; }

    // Cross-warp scan: 16 warp compositions.
    __shared__ float wa[TPB / 32];
    __shared__ float wb[TPB / 32];
    __shared__ float wcarry[TPB / 32];
    if (lane == 0) { wa[warp] = a; wb[warp] = b; }
    __syncthreads();
    if (warp == 0 && lane < (TPB / 32)) {
        float aa = wa[lane], bb = wb[lane];
#pragma unroll
        for (int off = 1; off < (TPB / 32); off <<= 1) {
            float ra = __shfl_down_sync(0x0000ffffu, aa, off);
            float rb = __shfl_down_sync(0x0000ffffu, bb, off);
            if (lane + off < (TPB / 32)) {
                bb = fmaf(aa, rb, bb);
                aa = aa * ra;
            }
        }
        // Carry entering warp `lane` from the right = inclusive(lane+1) applied to 0.
        float carry = __shfl_down_sync(0x0000ffffu, bb, 1);
        if (lane == (TPB / 32) - 1) carry = 0.f;
        wcarry[lane] = carry;
    }
    __syncthreads();

    // Carry entering this thread's chunk from the right.
    float g = fmaf(ea, wcarry[warp], eb);

    // Final sequential application within the chunk (reverse time order).
    float adv[EPT], ret[EPT];
#pragma unroll
    for (int j = EPT - 1; j >= 0; --j) {
        g = fmaf(c[j], g, d[j]);
        adv[j] = g;
        ret[j] = (mk[j] != 0.f) ? (g + v[j]) : 0.f;
    }

    *reinterpret_cast<float4*>(adv_out + base) = make_float4(adv[0], adv[1], adv[2], adv[3]);
    *reinterpret_cast<float4*>(ret_out + base) = make_float4(ret[0], ret[1], ret[2], ret[3]);
}

extern "C" void kernel_launch(void* const* d_in, const int* in_sizes, int n_in,
                              void* d_out, int out_size)
{
    const float* rewards = (const float*)d_in[0];
    const float* values  = (const float*)d_in[1];
    const int*   dones   = (const int*)d_in[2];
    const int*   mask    = (const int*)d_in[3];

    const int total = in_sizes[0];            // B * S
    const int B     = total / S_LEN;

    float* adv_out = (float*)d_out;
    float* ret_out = (float*)d_out + (long long)B * S_LEN;

    gae_kernel<<<B, TPB>>>(rewards, values, dones, mask, adv_out, ret_out);
}

// round 2
// speedup vs baseline: 1.0599x; 1.0599x over previous
#include <cuda_runtime.h>
#include <cuda_bf16.h>

// GAE backward affine suffix scan. Inputs: rewards f32 [B,S], values f32 [B,S],
// dones i32 [B,S], mask i32 [B,S] (prefix mask). Output: [advantages; returns].
//
//   nd    = 1 - done
//   delta = r + GAMMA * values[t+1]*mask[t+1] * nd - v
//   g[t]  = mask[t] ? (delta + GAMMA*LAMBDA*nd * g[t+1]) : 0
//   adv = g ; ret = mask ? g + v : 0
//
// Affine transform per step: T_t(g) = d_t + c_t*g with (c,d) = mask ? (GL*nd, delta) : (0,0).
// Composition (left = earlier in time): a = la*ra, b = lb + la*rb.

#define GAMMA  0.999f
#define LAMBDA 0.95f
#define GL     (GAMMA * LAMBDA)
#define S_LEN  2048
#define TPB    256
#define EPT    8           // TPB*EPT == S_LEN
#define NW     (TPB / 32)  // 8 warps

__global__ __launch_bounds__(TPB)
void gae_kernel(const float* __restrict__ rewards,
                const float* __restrict__ values,
                const int*   __restrict__ dones,
                const int*   __restrict__ mask,
                float* __restrict__ adv_out,
                float* __restrict__ ret_out)
{
    const int row  = blockIdx.x;
    const int tid  = threadIdx.x;
    const unsigned lane = tid & 31u;
    const unsigned warp = tid >> 5;

    const long long base = (long long)row * S_LEN + tid * EPT;

    // Coalesced streaming vector loads (touch-once data -> evict-first).
    const float4* rp = reinterpret_cast<const float4*>(rewards + base);
    const float4* vp = reinterpret_cast<const float4*>(values  + base);
    const int4*   dp = reinterpret_cast<const int4*>(dones + base);
    const int4*   mp = reinterpret_cast<const int4*>(mask  + base);
    float4 r4a = __ldcs(rp);     float4 r4b = __ldcs(rp + 1);
    float4 v4a = __ldcs(vp);     float4 v4b = __ldcs(vp + 1);
    int4   d4a = __ldcs(dp);     int4   d4b = __ldcs(dp + 1);
    int4   m4a = __ldcs(mp);     int4   m4b = __ldcs(mp + 1);

    // Neighbor (t+1) value/mask for last element of the chunk (L1 hit via the
    // next thread's already-fetched line, or zero past end-of-row).
    float v_next = 0.f, m_next = 0.f;
    if (tid * EPT + EPT < S_LEN) {
        v_next = __ldg(values + base + EPT);
        m_next = (float)__ldg(mask + base + EPT);
    }

    float r[EPT]  = {r4a.x, r4a.y, r4a.z, r4a.w, r4b.x, r4b.y, r4b.z, r4b.w};
    float v[EPT]  = {v4a.x, v4a.y, v4a.z, v4a.w, v4b.x, v4b.y, v4b.z, v4b.w};
    float nd[EPT] = {1.f - (float)d4a.x, 1.f - (float)d4a.y,
                     1.f - (float)d4a.z, 1.f - (float)d4a.w,
                     1.f - (float)d4b.x, 1.f - (float)d4b.y,
                     1.f - (float)d4b.z, 1.f - (float)d4b.w};
    float mk[EPT] = {(float)m4a.x, (float)m4a.y, (float)m4a.z, (float)m4a.w,
                     (float)m4b.x, (float)m4b.y, (float)m4b.z, (float)m4b.w};
    float nv[EPT]    = {v[1], v[2], v[3], v[4], v[5], v[6], v[7], v_next};
    float mnext[EPT] = {mk[1], mk[2], mk[3], mk[4], mk[5], mk[6], mk[7], m_next};

    // Per-element affine transforms (c, d); invalid steps -> (0, 0).
    float c[EPT], d[EPT];
#pragma unroll
    for (int j = 0; j < EPT; ++j) {
        float nvj   = nv[j] * mnext[j];
        float delta = fmaf(GAMMA * nd[j], nvj, r[j]) - v[j];
        c[j] = mk[j] * GL * nd[j];
        d[j] = mk[j] * delta;
    }

    // Thread-local composition over the 8 steps (reverse time order).
    float A = 1.f, Bc = 0.f;
#pragma unroll
    for (int j = EPT - 1; j >= 0; --j) {
        Bc = fmaf(c[j], Bc, d[j]);
        A  = c[j] * A;
    }

    // Warp-level inclusive suffix scan (Kogge-Stone, shfl_down).
    float a = A, b = Bc;
#pragma unroll
    for (int off = 1; off < 32; off <<= 1) {
        float ra = __shfl_down_sync(0xffffffffu, a, off);
        float rb = __shfl_down_sync(0xffffffffu, b, off);
        if (lane + off < 32) {
            b = fmaf(a, rb, b);
            a = a * ra;
        }
    }
    // Exclusive suffix within warp: E_i = inclusive(i+1); identity at lane 31.
    float ea = __shfl_down_sync(0xffffffffu, a, 1);
    float eb = __shfl_down_sync(0xffffffffu, b, 1);
    if (lane == 31) { ea = 1.f; eb = 0.f; }

    // Cross-warp scan over NW=8 warp aggregates.
    __shared__ float wa[NW];
    __shared__ float wb[NW];
    __shared__ float wcarry[NW];
    if (lane == 0) { wa[warp] = a; wb[warp] = b; }
    __syncthreads();
    if (warp == 0 && lane < NW) {
        float aa = wa[lane], bb = wb[lane];
#pragma unroll
        for (int off = 1; off < NW; off <<= 1) {
            float ra = __shfl_down_sync(0x000000ffu, aa, off);
            float rb = __shfl_down_sync(0x000000ffu, bb, off);
            if (lane + off < NW) {
                bb = fmaf(aa, rb, bb);
                aa = aa * ra;
            }
        }
        float carry = __shfl_down_sync(0x000000ffu, bb, 1);
        if (lane == NW - 1) carry = 0.f;
        wcarry[lane] = carry;
    }
    __syncthreads();

    // Carry entering this thread's chunk from the right, then final pass.
    float g = fmaf(ea, wcarry[warp], eb);

    float adv[EPT], ret[EPT];
#pragma unroll
    for (int j = EPT - 1; j >= 0; --j) {
        g = fmaf(c[j], g, d[j]);
        adv[j] = g;
        ret[j] = (mk[j] != 0.f) ? (g + v[j]) : 0.f;
    }

    float4* ap = reinterpret_cast<float4*>(adv_out + base);
    float4* tp = reinterpret_cast<float4*>(ret_out + base);
    __stcs(ap,     make_float4(adv[0], adv[1], adv[2], adv[3]));
    __stcs(ap + 1, make_float4(adv[4], adv[5], adv[6], adv[7]));
    __stcs(tp,     make_float4(ret[0], ret[1], ret[2], ret[3]));
    __stcs(tp + 1, make_float4(ret[4], ret[5], ret[6], ret[7]));
}

extern "C" void kernel_launch(void* const* d_in, const int* in_sizes, int n_in,
                              void* d_out, int out_size)
{
    const float* rewards = (const float*)d_in[0];
    const float* values  = (const float*)d_in[1];
    const int*   dones   = (const int*)d_in[2];
    const int*   mask    = (const int*)d_in[3];

    const int total = in_sizes[0];            // B * S
    const int B     = total / S_LEN;

    float* adv_out = (float*)d_out;
    float* ret_out = (float*)d_out + (long long)B * S_LEN;

    gae_kernel<<<B, TPB>>>(rewards, values, dones, mask, adv_out, ret_out);
}